// round 1
// baseline (speedup 1.0000x reference)
#include <cuda_runtime.h>
#include <cstdint>

#define NN 100000
#define EE 1600000
#define FF 128

// Scratch (static device globals — no allocation in kernel_launch)
__device__ float g_s[(size_t)NN * FF];   // segment-sum accumulator
__device__ float g_h1[(size_t)NN * FF];  // layer-1 output (post relu)
__device__ float g_deg[NN];              // degree, then 1/max(deg,1)

// ---------------------------------------------------------------------------
// Zero the accumulator (and optionally deg)
// ---------------------------------------------------------------------------
__global__ void k_zero(int zero_deg) {
    const int stride = gridDim.x * blockDim.x;
    int i = blockIdx.x * blockDim.x + threadIdx.x;
    float4* s4 = reinterpret_cast<float4*>(g_s);
    const int total4 = NN * FF / 4;
    for (int k = i; k < total4; k += stride)
        s4[k] = make_float4(0.f, 0.f, 0.f, 0.f);
    if (zero_deg) {
        for (int k = i; k < NN; k += stride)
            g_deg[k] = 0.f;
    }
}

// ---------------------------------------------------------------------------
// Edge scatter: one warp per edge, lane l handles float4 chunk l (32*4 = 128)
// s[dst] += w_e * h[src];   optionally deg[dst] += 1
// ---------------------------------------------------------------------------
template <bool ADD_DEG>
__global__ void k_scatter(const float* __restrict__ h,
                          const float* __restrict__ w,
                          const int* __restrict__ src,
                          const int* __restrict__ dst) {
    const int warp = (blockIdx.x * blockDim.x + threadIdx.x) >> 5;
    if (warp >= EE) return;
    const int lane = threadIdx.x & 31;

    const int sN = src[warp];
    const int dN = dst[warp];
    const float we = w[warp];

    const float4* hp = reinterpret_cast<const float4*>(h) + (size_t)sN * 32;
    float4 v = hp[lane];
    v.x *= we; v.y *= we; v.z *= we; v.w *= we;

    float4* sp = reinterpret_cast<float4*>(g_s) + (size_t)dN * 32;
    atomicAdd(sp + lane, v);   // sm_90+ vector atomic (REDG.128)

    if (ADD_DEG && lane == 0)
        atomicAdd(&g_deg[dN], 1.0f);
}

// ---------------------------------------------------------------------------
// deg -> 1 / max(deg, 1)
// ---------------------------------------------------------------------------
__global__ void k_invdeg() {
    int i = blockIdx.x * blockDim.x + threadIdx.x;
    if (i < NN) g_deg[i] = 1.0f / fmaxf(g_deg[i], 1.0f);
}

// ---------------------------------------------------------------------------
// Fused SAGE GEMM:
//   out[n][f] = act( sum_k X[n][k]*Ws[f][k] + sum_k (s[n][k]*invd[n])*Wn[f][k]
//               + bias[f] )
// Treated as one [N,256] x [256,128]^T GEMM, K-tiled by 32 (tiles 0..3 from
// X/Ws, tiles 4..7 from g_s/Wn). BM=BN=128, BK=32, 256 threads, 8x8 per
// thread as 2x(4-wide) chunks for conflict-light LDS.128.
// ---------------------------------------------------------------------------
template <bool RELU>
__global__ void k_gemm(const float* __restrict__ X,
                       const float* __restrict__ Ws,
                       const float* __restrict__ Wn,
                       const float* __restrict__ bias,
                       float* __restrict__ out) {
    __shared__ float As[32][128];
    __shared__ float Bs[32][128];

    const int tid = threadIdx.x;
    const int bm0 = blockIdx.x * 128;
    const int tm4 = (tid >> 4) * 4;   // 0,4,...,60
    const int tn4 = (tid & 15) * 4;   // 0,4,...,60

    float acc[8][8];
#pragma unroll
    for (int i = 0; i < 8; i++)
#pragma unroll
        for (int j = 0; j < 8; j++) acc[i][j] = 0.f;

    const float4* X4 = reinterpret_cast<const float4*>(X);
    const float4* S4 = reinterpret_cast<const float4*>(g_s);

#pragma unroll 1
    for (int kt = 0; kt < 8; kt++) {
        const bool from_s = (kt >= 4);
        const int kbase4 = (kt & 3) * 8;  // float4 col offset within 32-f4 row

        // --- load A tile (128 rows x 32 cols), transposed into As[k][m]
        const float4* a4 = from_s ? S4 : X4;
#pragma unroll
        for (int l = 0; l < 4; l++) {
            int idx = l * 256 + tid;      // 0..1023
            int r   = idx >> 3;           // 0..127
            int c4  = idx & 7;            // 0..7
            int gr  = bm0 + r;
            float4 v = make_float4(0.f, 0.f, 0.f, 0.f);
            if (gr < NN) {
                v = a4[(size_t)gr * 32 + kbase4 + c4];
                if (from_s) {
                    float inv = g_deg[gr];
                    v.x *= inv; v.y *= inv; v.z *= inv; v.w *= inv;
                }
            }
            int c = c4 * 4;
            As[c + 0][r] = v.x;
            As[c + 1][r] = v.y;
            As[c + 2][r] = v.z;
            As[c + 3][r] = v.w;
        }

        // --- load B tile: Bs[k][f] from Ws or Wn (row-major [128][128])
        const float4* w4 = reinterpret_cast<const float4*>(kt < 4 ? Ws : Wn);
#pragma unroll
        for (int l = 0; l < 4; l++) {
            int idx = l * 256 + tid;
            int f   = idx >> 3;
            int c4  = idx & 7;
            float4 v = w4[(size_t)f * 32 + kbase4 + c4];
            int c = c4 * 4;
            Bs[c + 0][f] = v.x;
            Bs[c + 1][f] = v.y;
            Bs[c + 2][f] = v.z;
            Bs[c + 3][f] = v.w;
        }

        __syncthreads();

#pragma unroll
        for (int k = 0; k < 32; k++) {
            float4 a0 = *reinterpret_cast<const float4*>(&As[k][tm4]);
            float4 a1 = *reinterpret_cast<const float4*>(&As[k][tm4 + 64]);
            float4 b0 = *reinterpret_cast<const float4*>(&Bs[k][tn4]);
            float4 b1 = *reinterpret_cast<const float4*>(&Bs[k][tn4 + 64]);
            float a[8] = {a0.x, a0.y, a0.z, a0.w, a1.x, a1.y, a1.z, a1.w};
            float b[8] = {b0.x, b0.y, b0.z, b0.w, b1.x, b1.y, b1.z, b1.w};
#pragma unroll
            for (int i = 0; i < 8; i++)
#pragma unroll
                for (int j = 0; j < 8; j++)
                    acc[i][j] = fmaf(a[i], b[j], acc[i][j]);
        }

        __syncthreads();
    }

    // --- epilogue: +bias, optional relu, vectorized store
    float4 bv0 = *reinterpret_cast<const float4*>(&bias[tn4]);
    float4 bv1 = *reinterpret_cast<const float4*>(&bias[tn4 + 64]);
    float bb[8] = {bv0.x, bv0.y, bv0.z, bv0.w, bv1.x, bv1.y, bv1.z, bv1.w};

    float4* out4 = reinterpret_cast<float4*>(out);
#pragma unroll
    for (int i = 0; i < 8; i++) {
        int gr = bm0 + ((i < 4) ? (tm4 + i) : (tm4 + 64 + (i - 4)));
        if (gr >= NN) continue;
        float o[8];
#pragma unroll
        for (int j = 0; j < 8; j++) {
            float v = acc[i][j] + bb[j];
            if (RELU) v = fmaxf(v, 0.f);
            o[j] = v;
        }
        out4[(size_t)gr * 32 + (tn4 >> 2)]      = make_float4(o[0], o[1], o[2], o[3]);
        out4[(size_t)gr * 32 + (tn4 >> 2) + 16] = make_float4(o[4], o[5], o[6], o[7]);
    }
}

// ---------------------------------------------------------------------------
// launch
// ---------------------------------------------------------------------------
extern "C" void kernel_launch(void* const* d_in, const int* in_sizes, int n_in,
                              void* d_out, int out_size) {
    const float* in_feat = (const float*)d_in[0];
    const float* weights = (const float*)d_in[1];
    const int*   src     = (const int*)d_in[2];
    const int*   dst     = (const int*)d_in[3];
    const float* Ws1     = (const float*)d_in[4];
    const float* b1      = (const float*)d_in[5];
    const float* Wn1     = (const float*)d_in[6];
    const float* Ws2     = (const float*)d_in[7];
    const float* b2      = (const float*)d_in[8];
    const float* Wn2     = (const float*)d_in[9];
    float* out = (float*)d_out;

    void* h1_ptr = nullptr;
    cudaGetSymbolAddress(&h1_ptr, g_h1);
    float* h1 = (float*)h1_ptr;

    const int scatter_blocks = (EE + 7) / 8;   // 8 warps (edges) per block
    const int gemm_blocks = (NN + 127) / 128;  // 782

    // Layer 1
    k_zero<<<1184, 256>>>(1);
    k_scatter<true><<<scatter_blocks, 256>>>(in_feat, weights, src, dst);
    k_invdeg<<<(NN + 255) / 256, 256>>>();
    k_gemm<true><<<gemm_blocks, 256>>>(in_feat, Ws1, Wn1, b1, h1);

    // Layer 2
    k_zero<<<1184, 256>>>(0);
    k_scatter<false><<<scatter_blocks, 256>>>(h1, weights, src, dst);
    k_gemm<false><<<gemm_blocks, 256>>>(h1, Ws2, Wn2, b2, out);
}

// round 2
// speedup vs baseline: 1.5521x; 1.5521x over previous
#include <cuda_runtime.h>
#include <cstdint>

#define NN 100000
#define EE 1600000

// Scratch (static device globals — no allocation in kernel_launch)
__device__ float g_s1[(size_t)NN * 128];  // layer-1 segment-sum accumulator
__device__ float g_s2[(size_t)NN * 128];  // layer-2 segment-sum accumulator
__device__ float g_h1[(size_t)NN * 128];  // layer-1 output (post relu)
__device__ float g_deg[NN];               // degree -> 1/max(deg,1)

// ---------------------------------------------------------------------------
// Edge scatter: one warp per edge, lane l handles float4 chunk l (32*4 = 128)
// s[dst] += w_e * h[src];   optionally deg[dst] += 1
// ---------------------------------------------------------------------------
template <bool ADD_DEG>
__global__ void k_scatter(const float* __restrict__ h,
                          const float* __restrict__ w,
                          const int* __restrict__ src,
                          const int* __restrict__ dst,
                          float* __restrict__ s) {
    const int warp = (blockIdx.x * blockDim.x + threadIdx.x) >> 5;
    if (warp >= EE) return;
    const int lane = threadIdx.x & 31;

    const int sN = src[warp];
    const int dN = dst[warp];
    const float we = w[warp];

    const float4* hp = reinterpret_cast<const float4*>(h) + (size_t)sN * 32;
    float4 v = hp[lane];
    v.x *= we; v.y *= we; v.z *= we; v.w *= we;

    float4* sp = reinterpret_cast<float4*>(s) + (size_t)dN * 32;
    atomicAdd(sp + lane, v);   // sm_90+ vector atomic (REDG.128)

    if (ADD_DEG && lane == 0)
        atomicAdd(&g_deg[dN], 1.0f);
}

// ---------------------------------------------------------------------------
// deg -> 1 / max(deg, 1)
// ---------------------------------------------------------------------------
__global__ void k_invdeg() {
    int i = blockIdx.x * blockDim.x + threadIdx.x;
    if (i < NN) g_deg[i] = 1.0f / fmaxf(g_deg[i], 1.0f);
}

// ---------------------------------------------------------------------------
// tf32 rounding helper (round-to-nearest, result is a valid fp32 bit pattern)
// ---------------------------------------------------------------------------
__device__ __forceinline__ float f2tf32(float x) {
    unsigned r;
    asm("cvt.rna.tf32.f32 %0, %1;" : "=r"(r) : "f"(x));
    return __uint_as_float(r);
}

__device__ __forceinline__ void mma_tf32(float c[4],
                                         const unsigned a[4],
                                         const unsigned b[2]) {
    asm volatile(
        "mma.sync.aligned.m16n8k8.row.col.f32.tf32.tf32.f32 "
        "{%0,%1,%2,%3}, {%4,%5,%6,%7}, {%8,%9}, {%0,%1,%2,%3};"
        : "+f"(c[0]), "+f"(c[1]), "+f"(c[2]), "+f"(c[3])
        : "r"(a[0]), "r"(a[1]), "r"(a[2]), "r"(a[3]),
          "r"(b[0]), "r"(b[1]));
}

// ---------------------------------------------------------------------------
// Fused SAGE GEMM (tf32 tensor cores):
//   out[n][f] = act( X[n]·Ws[f] + (s[n]*rdeg[n])·Wn[f] + bias[f] )
// One [N,256] x [256,128]^T GEMM; K-tiles 0..3 from X/Ws, 4..7 from s/Wn.
// BM=128, BN=128, BK=32. 8 warps, warp tile 64(M)x32(N), mma.m16n8k8 tf32.
// As/Bs stride 36 -> fragment LDS is bank-conflict-free.
// ---------------------------------------------------------------------------
template <bool RELU>
__global__ void __launch_bounds__(256, 2)
k_gemm_tf32(const float* __restrict__ X,
            const float* __restrict__ S,
            const float* __restrict__ rdeg,
            const float* __restrict__ Ws,
            const float* __restrict__ Wn,
            const float* __restrict__ bias,
            float* __restrict__ out) {
    __shared__ float As[128][36];  // [m][k]
    __shared__ float Bs[128][36];  // [n(=f)][k]

    const int tid  = threadIdx.x;
    const int bm0  = blockIdx.x * 128;
    const int wid  = tid >> 5;
    const int lane = tid & 31;
    const int wm   = (wid & 1) * 64;   // warp M offset
    const int wn   = (wid >> 1) * 32;  // warp N offset
    const int gr   = lane >> 2;        // 0..7
    const int gc   = lane & 3;         // 0..3

    float acc[4][4][4];
#pragma unroll
    for (int mi = 0; mi < 4; mi++)
#pragma unroll
        for (int ni = 0; ni < 4; ni++)
#pragma unroll
            for (int c = 0; c < 4; c++) acc[mi][ni][c] = 0.f;

#pragma unroll 1
    for (int kt = 0; kt < 8; kt++) {
        const bool from_s = (kt >= 4);
        const float4* a4 = reinterpret_cast<const float4*>(from_s ? S : X);
        const float4* w4 = reinterpret_cast<const float4*>(from_s ? Wn : Ws);
        const int kb4 = (kt & 3) * 8;  // float4 col offset within the 32-f4 row

        // --- stage A tile (128 x 32) into As, tf32-rounded
#pragma unroll
        for (int l = 0; l < 4; l++) {
            int idx = l * 256 + tid;   // 0..1023
            int r   = idx >> 3;        // 0..127
            int c4  = idx & 7;         // 0..7
            int grow = bm0 + r;
            float4 v = make_float4(0.f, 0.f, 0.f, 0.f);
            if (grow < NN) {
                v = a4[(size_t)grow * 32 + kb4 + c4];
                if (from_s) {
                    float iv = rdeg[grow];
                    v.x *= iv; v.y *= iv; v.z *= iv; v.w *= iv;
                }
            }
            int c = c4 * 4;
            As[r][c + 0] = f2tf32(v.x);
            As[r][c + 1] = f2tf32(v.y);
            As[r][c + 2] = f2tf32(v.z);
            As[r][c + 3] = f2tf32(v.w);
        }

        // --- stage B tile (128 x 32) into Bs, tf32-rounded
#pragma unroll
        for (int l = 0; l < 4; l++) {
            int idx = l * 256 + tid;
            int f   = idx >> 3;
            int c4  = idx & 7;
            float4 v = w4[(size_t)f * 32 + kb4 + c4];
            int c = c4 * 4;
            Bs[f][c + 0] = f2tf32(v.x);
            Bs[f][c + 1] = f2tf32(v.y);
            Bs[f][c + 2] = f2tf32(v.z);
            Bs[f][c + 3] = f2tf32(v.w);
        }

        __syncthreads();

#pragma unroll
        for (int ks = 0; ks < 4; ks++) {
            const int k0 = ks * 8;

            unsigned a[4][4];
#pragma unroll
            for (int mi = 0; mi < 4; mi++) {
                int r = wm + mi * 16 + gr;
                a[mi][0] = __float_as_uint(As[r][k0 + gc]);
                a[mi][1] = __float_as_uint(As[r + 8][k0 + gc]);
                a[mi][2] = __float_as_uint(As[r][k0 + gc + 4]);
                a[mi][3] = __float_as_uint(As[r + 8][k0 + gc + 4]);
            }

            unsigned b[4][2];
#pragma unroll
            for (int ni = 0; ni < 4; ni++) {
                int n = wn + ni * 8 + gr;  // b fragment col = lane>>2
                b[ni][0] = __float_as_uint(Bs[n][k0 + gc]);
                b[ni][1] = __float_as_uint(Bs[n][k0 + gc + 4]);
            }

#pragma unroll
            for (int mi = 0; mi < 4; mi++)
#pragma unroll
                for (int ni = 0; ni < 4; ni++)
                    mma_tf32(acc[mi][ni], a[mi], b[ni]);
        }

        __syncthreads();
    }

    // --- epilogue: +bias, optional relu, float2 stores (32B sector aligned)
#pragma unroll
    for (int ni = 0; ni < 4; ni++) {
        int col = wn + ni * 8 + gc * 2;
        float b0 = bias[col];
        float b1 = bias[col + 1];
#pragma unroll
        for (int mi = 0; mi < 4; mi++) {
            int r0 = bm0 + wm + mi * 16 + gr;
            float2 v0, v1;
            v0.x = acc[mi][ni][0] + b0;
            v0.y = acc[mi][ni][1] + b1;
            v1.x = acc[mi][ni][2] + b0;
            v1.y = acc[mi][ni][3] + b1;
            if (RELU) {
                v0.x = fmaxf(v0.x, 0.f); v0.y = fmaxf(v0.y, 0.f);
                v1.x = fmaxf(v1.x, 0.f); v1.y = fmaxf(v1.y, 0.f);
            }
            if (r0 < NN)
                *reinterpret_cast<float2*>(&out[(size_t)r0 * 128 + col]) = v0;
            if (r0 + 8 < NN)
                *reinterpret_cast<float2*>(&out[(size_t)(r0 + 8) * 128 + col]) = v1;
        }
    }
}

// ---------------------------------------------------------------------------
// launch
// ---------------------------------------------------------------------------
extern "C" void kernel_launch(void* const* d_in, const int* in_sizes, int n_in,
                              void* d_out, int out_size) {
    const float* in_feat = (const float*)d_in[0];
    const float* weights = (const float*)d_in[1];
    const int*   src     = (const int*)d_in[2];
    const int*   dst     = (const int*)d_in[3];
    const float* Ws1     = (const float*)d_in[4];
    const float* b1      = (const float*)d_in[5];
    const float* Wn1     = (const float*)d_in[6];
    const float* Ws2     = (const float*)d_in[7];
    const float* b2      = (const float*)d_in[8];
    const float* Wn2     = (const float*)d_in[9];
    float* out = (float*)d_out;

    void *p_s1, *p_s2, *p_h1, *p_deg;
    cudaGetSymbolAddress(&p_s1, g_s1);
    cudaGetSymbolAddress(&p_s2, g_s2);
    cudaGetSymbolAddress(&p_h1, g_h1);
    cudaGetSymbolAddress(&p_deg, g_deg);
    float* s1 = (float*)p_s1;
    float* s2 = (float*)p_s2;
    float* h1 = (float*)p_h1;
    float* deg = (float*)p_deg;

    const int scatter_blocks = (EE + 7) / 8;   // 8 warps (edges) per block
    const int gemm_blocks = (NN + 127) / 128;  // 782

    // Zero both accumulators + deg upfront (memset graph nodes)
    cudaMemsetAsync(s1, 0, (size_t)NN * 128 * sizeof(float), 0);
    cudaMemsetAsync(s2, 0, (size_t)NN * 128 * sizeof(float), 0);
    cudaMemsetAsync(deg, 0, (size_t)NN * sizeof(float), 0);

    // Layer 1
    k_scatter<true><<<scatter_blocks, 256>>>(in_feat, weights, src, dst, s1);
    k_invdeg<<<(NN + 255) / 256, 256>>>();
    k_gemm_tf32<true><<<gemm_blocks, 256>>>(in_feat, s1, deg, Ws1, Wn1, b1, h1);

    // Layer 2
    k_scatter<false><<<scatter_blocks, 256>>>(h1, weights, src, dst, s2);
    k_gemm_tf32<false><<<gemm_blocks, 256>>>(h1, s2, deg, Ws2, Wn2, b2, out);
}

// round 3
// speedup vs baseline: 2.8304x; 1.8235x over previous
#include <cuda_runtime.h>
#include <cstdint>

#define NN 100000
#define EE 1600000
#define SCAN_BLOCKS 391   // ceil(NN/256)

// Scratch (static device globals — no allocation in kernel_launch)
__device__ float g_s[(size_t)NN * 128];    // neigh (mean-aggregated) buffer
__device__ float g_h1[(size_t)NN * 128];   // layer-1 output (post relu)
__device__ int   g_cnt[NN];                // dst histogram (= in-degree)
__device__ int   g_excl[NN];               // within-block exclusive scan
__device__ int   g_blocksum[512];          // per-block totals
__device__ int   g_rowstart[NN + 1];       // CSR row offsets
__device__ int   g_cursor[NN];             // fill cursors
__device__ int2  g_elist[EE];              // {src, weight_bits} grouped by dst

// ---------------------------------------------------------------------------
// CSR build: histogram -> scan -> fill
// ---------------------------------------------------------------------------
__global__ void k_hist(const int* __restrict__ dst) {
    int e = blockIdx.x * blockDim.x + threadIdx.x;
    if (e < EE) atomicAdd(&g_cnt[dst[e]], 1);
}

__global__ void k_scanA() {
    __shared__ int sm[256];
    int i = blockIdx.x * 256 + threadIdx.x;
    int v = (i < NN) ? g_cnt[i] : 0;
    sm[threadIdx.x] = v;
    __syncthreads();
#pragma unroll
    for (int ofs = 1; ofs < 256; ofs <<= 1) {
        int t = (threadIdx.x >= ofs) ? sm[threadIdx.x - ofs] : 0;
        __syncthreads();
        sm[threadIdx.x] += t;
        __syncthreads();
    }
    if (i < NN) g_excl[i] = sm[threadIdx.x] - v;
    if (threadIdx.x == 255) g_blocksum[blockIdx.x] = sm[255];
}

__global__ void k_scanB() {
    __shared__ int sm[512];
    int v = (threadIdx.x < SCAN_BLOCKS) ? g_blocksum[threadIdx.x] : 0;
    sm[threadIdx.x] = v;
    __syncthreads();
#pragma unroll
    for (int ofs = 1; ofs < 512; ofs <<= 1) {
        int t = (threadIdx.x >= ofs) ? sm[threadIdx.x - ofs] : 0;
        __syncthreads();
        sm[threadIdx.x] += t;
        __syncthreads();
    }
    if (threadIdx.x < SCAN_BLOCKS) g_blocksum[threadIdx.x] = sm[threadIdx.x] - v;
}

__global__ void k_scanC() {
    int i = blockIdx.x * 256 + threadIdx.x;
    if (i < NN) {
        int rs = g_excl[i] + g_blocksum[blockIdx.x];
        g_rowstart[i] = rs;
        g_cursor[i] = rs;
    }
    if (i == 0) g_rowstart[NN] = EE;
}

__global__ void k_fill(const int* __restrict__ src,
                       const int* __restrict__ dst,
                       const float* __restrict__ w) {
    int e = blockIdx.x * blockDim.x + threadIdx.x;
    if (e >= EE) return;
    int pos = atomicAdd(&g_cursor[dst[e]], 1);
    g_elist[pos] = make_int2(src[e], __float_as_int(w[e]));
}

// ---------------------------------------------------------------------------
// Gather-aggregate: one warp per dst node; lane l owns float4 chunk l.
// neigh[n] = (1/max(deg,1)) * sum_{e in CSR[n]} w_e * h[src_e]
// ---------------------------------------------------------------------------
__global__ void k_gather(const float* __restrict__ h,
                         float* __restrict__ neigh) {
    const int n = (blockIdx.x * blockDim.x + threadIdx.x) >> 5;
    if (n >= NN) return;
    const int lane = threadIdx.x & 31;

    const int start = g_rowstart[n];
    const int end   = g_rowstart[n + 1];

    const float4* h4 = reinterpret_cast<const float4*>(h);

    float4 acc0 = make_float4(0.f, 0.f, 0.f, 0.f);
    float4 acc1 = make_float4(0.f, 0.f, 0.f, 0.f);

    int i = start;
    for (; i + 1 < end; i += 2) {
        int2 e0 = g_elist[i];
        int2 e1 = g_elist[i + 1];
        float w0 = __int_as_float(e0.y);
        float w1 = __int_as_float(e1.y);
        float4 v0 = h4[(size_t)e0.x * 32 + lane];
        float4 v1 = h4[(size_t)e1.x * 32 + lane];
        acc0.x = fmaf(w0, v0.x, acc0.x); acc0.y = fmaf(w0, v0.y, acc0.y);
        acc0.z = fmaf(w0, v0.z, acc0.z); acc0.w = fmaf(w0, v0.w, acc0.w);
        acc1.x = fmaf(w1, v1.x, acc1.x); acc1.y = fmaf(w1, v1.y, acc1.y);
        acc1.z = fmaf(w1, v1.z, acc1.z); acc1.w = fmaf(w1, v1.w, acc1.w);
    }
    if (i < end) {
        int2 e0 = g_elist[i];
        float w0 = __int_as_float(e0.y);
        float4 v0 = h4[(size_t)e0.x * 32 + lane];
        acc0.x = fmaf(w0, v0.x, acc0.x); acc0.y = fmaf(w0, v0.y, acc0.y);
        acc0.z = fmaf(w0, v0.z, acc0.z); acc0.w = fmaf(w0, v0.w, acc0.w);
    }

    int deg = end - start;
    float inv = 1.0f / (float)max(deg, 1);
    float4 r;
    r.x = (acc0.x + acc1.x) * inv;
    r.y = (acc0.y + acc1.y) * inv;
    r.z = (acc0.z + acc1.z) * inv;
    r.w = (acc0.w + acc1.w) * inv;
    reinterpret_cast<float4*>(neigh)[(size_t)n * 32 + lane] = r;
}

// ---------------------------------------------------------------------------
// tf32 helpers
// ---------------------------------------------------------------------------
__device__ __forceinline__ float f2tf32(float x) {
    unsigned r;
    asm("cvt.rna.tf32.f32 %0, %1;" : "=r"(r) : "f"(x));
    return __uint_as_float(r);
}

__device__ __forceinline__ void mma_tf32(float c[4],
                                         const unsigned a[4],
                                         const unsigned b[2]) {
    asm volatile(
        "mma.sync.aligned.m16n8k8.row.col.f32.tf32.tf32.f32 "
        "{%0,%1,%2,%3}, {%4,%5,%6,%7}, {%8,%9}, {%0,%1,%2,%3};"
        : "+f"(c[0]), "+f"(c[1]), "+f"(c[2]), "+f"(c[3])
        : "r"(a[0]), "r"(a[1]), "r"(a[2]), "r"(a[3]),
          "r"(b[0]), "r"(b[1]));
}

// ---------------------------------------------------------------------------
// Fused SAGE GEMM (tf32 tensor cores):
//   out[n][f] = act( X[n]·Ws[f] + neigh[n]·Wn[f] + bias[f] )
// ---------------------------------------------------------------------------
template <bool RELU>
__global__ void __launch_bounds__(256, 2)
k_gemm_tf32(const float* __restrict__ X,
            const float* __restrict__ S,
            const float* __restrict__ Ws,
            const float* __restrict__ Wn,
            const float* __restrict__ bias,
            float* __restrict__ out) {
    __shared__ float As[128][36];  // [m][k]
    __shared__ float Bs[128][36];  // [n(=f)][k]

    const int tid  = threadIdx.x;
    const int bm0  = blockIdx.x * 128;
    const int wid  = tid >> 5;
    const int lane = tid & 31;
    const int wm   = (wid & 1) * 64;
    const int wn   = (wid >> 1) * 32;
    const int gr   = lane >> 2;
    const int gc   = lane & 3;

    float acc[4][4][4];
#pragma unroll
    for (int mi = 0; mi < 4; mi++)
#pragma unroll
        for (int ni = 0; ni < 4; ni++)
#pragma unroll
            for (int c = 0; c < 4; c++) acc[mi][ni][c] = 0.f;

#pragma unroll 1
    for (int kt = 0; kt < 8; kt++) {
        const bool from_s = (kt >= 4);
        const float4* a4 = reinterpret_cast<const float4*>(from_s ? S : X);
        const float4* w4 = reinterpret_cast<const float4*>(from_s ? Wn : Ws);
        const int kb4 = (kt & 3) * 8;

#pragma unroll
        for (int l = 0; l < 4; l++) {
            int idx = l * 256 + tid;
            int r   = idx >> 3;
            int c4  = idx & 7;
            int grow = bm0 + r;
            float4 v = make_float4(0.f, 0.f, 0.f, 0.f);
            if (grow < NN) v = a4[(size_t)grow * 32 + kb4 + c4];
            int c = c4 * 4;
            As[r][c + 0] = f2tf32(v.x);
            As[r][c + 1] = f2tf32(v.y);
            As[r][c + 2] = f2tf32(v.z);
            As[r][c + 3] = f2tf32(v.w);
        }

#pragma unroll
        for (int l = 0; l < 4; l++) {
            int idx = l * 256 + tid;
            int f   = idx >> 3;
            int c4  = idx & 7;
            float4 v = w4[(size_t)f * 32 + kb4 + c4];
            int c = c4 * 4;
            Bs[f][c + 0] = f2tf32(v.x);
            Bs[f][c + 1] = f2tf32(v.y);
            Bs[f][c + 2] = f2tf32(v.z);
            Bs[f][c + 3] = f2tf32(v.w);
        }

        __syncthreads();

#pragma unroll
        for (int ks = 0; ks < 4; ks++) {
            const int k0 = ks * 8;

            unsigned a[4][4];
#pragma unroll
            for (int mi = 0; mi < 4; mi++) {
                int r = wm + mi * 16 + gr;
                a[mi][0] = __float_as_uint(As[r][k0 + gc]);
                a[mi][1] = __float_as_uint(As[r + 8][k0 + gc]);
                a[mi][2] = __float_as_uint(As[r][k0 + gc + 4]);
                a[mi][3] = __float_as_uint(As[r + 8][k0 + gc + 4]);
            }

            unsigned b[4][2];
#pragma unroll
            for (int ni = 0; ni < 4; ni++) {
                int n = wn + ni * 8 + gr;
                b[ni][0] = __float_as_uint(Bs[n][k0 + gc]);
                b[ni][1] = __float_as_uint(Bs[n][k0 + gc + 4]);
            }

#pragma unroll
            for (int mi = 0; mi < 4; mi++)
#pragma unroll
                for (int ni = 0; ni < 4; ni++)
                    mma_tf32(acc[mi][ni], a[mi], b[ni]);
        }

        __syncthreads();
    }

#pragma unroll
    for (int ni = 0; ni < 4; ni++) {
        int col = wn + ni * 8 + gc * 2;
        float b0 = bias[col];
        float b1 = bias[col + 1];
#pragma unroll
        for (int mi = 0; mi < 4; mi++) {
            int r0 = bm0 + wm + mi * 16 + gr;
            float2 v0, v1;
            v0.x = acc[mi][ni][0] + b0;
            v0.y = acc[mi][ni][1] + b1;
            v1.x = acc[mi][ni][2] + b0;
            v1.y = acc[mi][ni][3] + b1;
            if (RELU) {
                v0.x = fmaxf(v0.x, 0.f); v0.y = fmaxf(v0.y, 0.f);
                v1.x = fmaxf(v1.x, 0.f); v1.y = fmaxf(v1.y, 0.f);
            }
            if (r0 < NN)
                *reinterpret_cast<float2*>(&out[(size_t)r0 * 128 + col]) = v0;
            if (r0 + 8 < NN)
                *reinterpret_cast<float2*>(&out[(size_t)(r0 + 8) * 128 + col]) = v1;
        }
    }
}

// ---------------------------------------------------------------------------
// launch
// ---------------------------------------------------------------------------
extern "C" void kernel_launch(void* const* d_in, const int* in_sizes, int n_in,
                              void* d_out, int out_size) {
    const float* in_feat = (const float*)d_in[0];
    const float* weights = (const float*)d_in[1];
    const int*   src     = (const int*)d_in[2];
    const int*   dst     = (const int*)d_in[3];
    const float* Ws1     = (const float*)d_in[4];
    const float* b1      = (const float*)d_in[5];
    const float* Wn1     = (const float*)d_in[6];
    const float* Ws2     = (const float*)d_in[7];
    const float* b2      = (const float*)d_in[8];
    const float* Wn2     = (const float*)d_in[9];
    float* out = (float*)d_out;

    void *p_s, *p_h1, *p_cnt;
    cudaGetSymbolAddress(&p_s, g_s);
    cudaGetSymbolAddress(&p_h1, g_h1);
    cudaGetSymbolAddress(&p_cnt, g_cnt);
    float* s  = (float*)p_s;
    float* h1 = (float*)p_h1;

    const int eb = (EE + 255) / 256;            // edge-parallel blocks
    const int gather_blocks = (NN * 32 + 255) / 256;  // 1 warp per node
    const int gemm_blocks = (NN + 127) / 128;

    // --- CSR build (once, shared by both layers)
    cudaMemsetAsync(p_cnt, 0, NN * sizeof(int), 0);
    k_hist<<<eb, 256>>>(dst);
    k_scanA<<<SCAN_BLOCKS, 256>>>();
    k_scanB<<<1, 512>>>();
    k_scanC<<<SCAN_BLOCKS, 256>>>();
    k_fill<<<eb, 256>>>(src, dst, weights);

    // --- Layer 1
    k_gather<<<gather_blocks, 256>>>(in_feat, s);
    k_gemm_tf32<true><<<gemm_blocks, 256>>>(in_feat, s, Ws1, Wn1, b1, h1);

    // --- Layer 2
    k_gather<<<gather_blocks, 256>>>(h1, s);
    k_gemm_tf32<false><<<gemm_blocks, 256>>>(h1, s, Ws2, Wn2, b2, out);
}